// round 3
// baseline (speedup 1.0000x reference)
#include <cuda_runtime.h>
#include <cuda_bf16.h>
#include <cstdint>

// ===================== problem dims =====================
#define BDIM 4096
#define IDIM 1024
#define HDIM 1024
#define KDIM 2048   // I + H
#define NDIM 4096   // 4 * H  (gate-major: n = g*1024 + j, g in {f,i,o,c})

// ===================== device scratch (static, allowed) =====================
__device__ __align__(256) __nv_bfloat16 g_Ahi[(size_t)BDIM * KDIM];
__device__ __align__(256) __nv_bfloat16 g_Alo[(size_t)BDIM * KDIM];
__device__ __align__(256) __nv_bfloat16 g_Whi[(size_t)NDIM * KDIM];
__device__ __align__(256) __nv_bfloat16 g_Wlo[(size_t)NDIM * KDIM];
__device__ __align__(256) float         g_gates[(size_t)BDIM * NDIM];
__device__ __align__(256) float         g_bias[NDIM];
__device__ __align__(256) float         g_mask[BDIM];

// ===================== small PTX helpers (sm_80+ features only) =====================
__device__ __forceinline__ uint32_t smem_to_u32(const void* p) {
    uint32_t a;
    asm("{ .reg .u64 t; cvta.to.shared.u64 t, %1; cvt.u32.u64 %0, t; }" : "=r"(a) : "l"(p));
    return a;
}

__device__ __forceinline__ void cp16(uint32_t saddr, const void* g) {
    asm volatile("cp.async.cg.shared.global [%0], [%1], 16;" :: "r"(saddr), "l"(g) : "memory");
}

#define CP_COMMIT() asm volatile("cp.async.commit_group;" ::: "memory")
#define CP_WAIT(N)  asm volatile("cp.async.wait_group %0;" :: "n"(N) : "memory")

__device__ __forceinline__ void ldsm4(uint32_t* r, uint32_t addr) {
    asm volatile("ldmatrix.sync.aligned.m8n8.x4.shared.b16 {%0,%1,%2,%3}, [%4];"
                 : "=r"(r[0]), "=r"(r[1]), "=r"(r[2]), "=r"(r[3]) : "r"(addr));
}

__device__ __forceinline__ void mma16816(float* c, const uint32_t* a, uint32_t b0, uint32_t b1) {
    asm volatile(
        "mma.sync.aligned.m16n8k16.row.col.f32.bf16.bf16.f32 "
        "{%0,%1,%2,%3}, {%4,%5,%6,%7}, {%8,%9}, {%0,%1,%2,%3};"
        : "+f"(c[0]), "+f"(c[1]), "+f"(c[2]), "+f"(c[3])
        : "r"(a[0]), "r"(a[1]), "r"(a[2]), "r"(a[3]), "r"(b0), "r"(b1));
}

// ===================== split-bf16 helpers =====================
__device__ __forceinline__ uint32_t pk2(__nv_bfloat16 a, __nv_bfloat16 b) {
    __nv_bfloat162 t = __halves2bfloat162(a, b);
    return *reinterpret_cast<uint32_t*>(&t);
}

// split float4 into bf16 hi + bf16 lo, store 4+4 bf16; returns sum of squares
__device__ __forceinline__ float split_store4(float4 v, __nv_bfloat16* hip, __nv_bfloat16* lop) {
    __nv_bfloat16 h0 = __float2bfloat16(v.x), h1 = __float2bfloat16(v.y),
                  h2 = __float2bfloat16(v.z), h3 = __float2bfloat16(v.w);
    float l0 = v.x - __bfloat162float(h0), l1 = v.y - __bfloat162float(h1),
          l2 = v.z - __bfloat162float(h2), l3 = v.w - __bfloat162float(h3);
    uint2 hv = make_uint2(pk2(h0, h1), pk2(h2, h3));
    uint2 lv = make_uint2(pk2(__float2bfloat16(l0), __float2bfloat16(l1)),
                          pk2(__float2bfloat16(l2), __float2bfloat16(l3)));
    *reinterpret_cast<uint2*>(hip) = hv;
    *reinterpret_cast<uint2*>(lop) = lv;
    return v.x * v.x + v.y * v.y + v.z * v.z + v.w * v.w;
}

// ===================== kernel 1: convert A = [x | h_prev] =====================
__global__ void convert_A_kernel(const float* __restrict__ x, const float* __restrict__ h) {
    int m = blockIdx.x;
    int t = threadIdx.x;  // 256 threads, one float4 each per half
    float4 vx = reinterpret_cast<const float4*>(x)[(size_t)m * 256 + t];
    float ss = split_store4(vx, g_Ahi + (size_t)m * KDIM + 4 * t,
                                g_Alo + (size_t)m * KDIM + 4 * t);
    float4 vh = reinterpret_cast<const float4*>(h)[(size_t)m * 256 + t];
    split_store4(vh, g_Ahi + (size_t)m * KDIM + IDIM + 4 * t,
                     g_Alo + (size_t)m * KDIM + IDIM + 4 * t);

    __shared__ float red[256];
    red[t] = ss;
    __syncthreads();
    for (int s = 128; s > 0; s >>= 1) {
        if (t < s) red[t] += red[t + s];
        __syncthreads();
    }
    if (t == 0) g_mask[m] = (red[0] > 1e-6f) ? 1.0f : 0.0f;  // norm > 0.001
}

// ===================== kernel 2: convert packed weights =====================
__global__ void convert_W_kernel(const float* __restrict__ Wf, const float* __restrict__ Wi,
                                 const float* __restrict__ Wo, const float* __restrict__ Wc,
                                 const float* __restrict__ Vf, const float* __restrict__ Vi,
                                 const float* __restrict__ Vo, const float* __restrict__ Vc) {
    int n = blockIdx.x;     // 0..4095, gate-major
    int t = threadIdx.x;    // 256
    int g = n >> 10, j = n & 1023;
    const float* W = (g == 0) ? Wf : (g == 1) ? Wi : (g == 2) ? Wo : Wc;
    const float* V = (g == 0) ? Vf : (g == 1) ? Vi : (g == 2) ? Vo : Vc;
    float4 vw = reinterpret_cast<const float4*>(W)[(size_t)j * 256 + t];
    split_store4(vw, g_Whi + (size_t)n * KDIM + 4 * t,
                     g_Wlo + (size_t)n * KDIM + 4 * t);
    float4 vv = reinterpret_cast<const float4*>(V)[(size_t)j * 256 + t];
    split_store4(vv, g_Whi + (size_t)n * KDIM + IDIM + 4 * t,
                     g_Wlo + (size_t)n * KDIM + IDIM + 4 * t);
}

// ===================== kernel 3: combined bias =====================
__global__ void bias_kernel(const float* __restrict__ bWf, const float* __restrict__ bVf, const float* __restrict__ bf_,
                            const float* __restrict__ bWi, const float* __restrict__ bVi, const float* __restrict__ bi_,
                            const float* __restrict__ bWo, const float* __restrict__ bVo, const float* __restrict__ bo_,
                            const float* __restrict__ bWc, const float* __restrict__ bVc, const float* __restrict__ bc_) {
    int n = blockIdx.x * blockDim.x + threadIdx.x;
    if (n >= NDIM) return;
    int g = n >> 10, j = n & 1023;
    const float* a = (g == 0) ? bWf : (g == 1) ? bWi : (g == 2) ? bWo : bWc;
    const float* b = (g == 0) ? bVf : (g == 1) ? bVi : (g == 2) ? bVo : bVc;
    const float* c = (g == 0) ? bf_ : (g == 1) ? bi_ : (g == 2) ? bo_ : bc_;
    g_bias[n] = a[j] + b[j] + c[j];
}

// ===================== kernel 4: pipelined mma.sync GEMM =====================
// gates[4096,4096] = Ahi*Whi^T + Ahi*Wlo^T + Alo*Whi^T   (fp32 accum)
#define BM 128
#define BN 128
#define BK 32           // bf16 elems; 64 bytes per row per k-tile
#define NK (KDIM / BK)  // 64 k-tiles
#define TPITCH 80       // 64B data + 16B pad -> conflict-free ldmatrix
#define BUF_BYTES (128 * TPITCH)       // 10240 per operand buffer
#define STAGE_BYTES (4 * BUF_BYTES)    // Ahi, Alo, Whi, Wlo
#define GEMM_SMEM (2 * STAGE_BYTES)    // 81920 (2 stages)

__device__ __forceinline__ void load_stage(uint32_t s0, int kt, int tid,
                                           const __nv_bfloat16* Ahi, const __nv_bfloat16* Alo,
                                           const __nv_bfloat16* Whi, const __nv_bfloat16* Wlo) {
    #pragma unroll
    for (int i = 0; i < 2; ++i) {
        int q = tid + i * 256;
        int r = q >> 2, c = q & 3;                    // row 0..127, 16B chunk 0..3
        size_t goff = (size_t)r * KDIM + (size_t)kt * BK + c * 8;
        uint32_t soff = (uint32_t)(r * TPITCH + c * 16);
        cp16(s0 + soff,                 Ahi + goff);
        cp16(s0 + BUF_BYTES + soff,     Alo + goff);
        cp16(s0 + 2 * BUF_BYTES + soff, Whi + goff);
        cp16(s0 + 3 * BUF_BYTES + soff, Wlo + goff);
    }
    CP_COMMIT();
}

__global__ void __launch_bounds__(256, 2) gemm_kernel() {
    extern __shared__ char smem[];
    uint32_t sb = smem_to_u32(smem);
    int tid = threadIdx.x, wid = tid >> 5, lid = tid & 31;
    int m0 = blockIdx.y * BM;
    int n0 = blockIdx.x * BN;
    int wm = (wid >> 1) * 32;   // warp m offset within CTA tile (4 warps)
    int wn = (wid & 1) * 64;    // warp n offset within CTA tile (2 warps)

    const __nv_bfloat16* Ahi = g_Ahi + (size_t)m0 * KDIM;
    const __nv_bfloat16* Alo = g_Alo + (size_t)m0 * KDIM;
    const __nv_bfloat16* Whi = g_Whi + (size_t)n0 * KDIM;
    const __nv_bfloat16* Wlo = g_Wlo + (size_t)n0 * KDIM;

    float acc[2][8][4];
    #pragma unroll
    for (int i = 0; i < 2; ++i)
        #pragma unroll
        for (int j = 0; j < 8; ++j)
            #pragma unroll
            for (int k = 0; k < 4; ++k) acc[i][j][k] = 0.0f;

    // per-thread ldmatrix row/chunk components
    int lrow = lid & 15;                  // row within 16-row tile pair
    uint32_t lchunk = (uint32_t)((lid >> 4) << 4);  // +16B for second k-chunk

    load_stage(sb, 0, tid, Ahi, Alo, Whi, Wlo);

    for (int kt = 0; kt < NK; ++kt) {
        uint32_t cur = sb + (uint32_t)(kt & 1) * STAGE_BYTES;
        if (kt + 1 < NK)
            load_stage(sb + (uint32_t)((kt + 1) & 1) * STAGE_BYTES, kt + 1, tid,
                       Ahi, Alo, Whi, Wlo);
        if (kt + 1 < NK) { CP_WAIT(1); } else { CP_WAIT(0); }
        __syncthreads();

        uint32_t sAhi = cur;
        uint32_t sAlo = cur + BUF_BYTES;
        uint32_t sWhi = cur + 2 * BUF_BYTES;
        uint32_t sWlo = cur + 3 * BUF_BYTES;

        #pragma unroll
        for (int ks = 0; ks < 2; ++ks) {
            uint32_t kb = (uint32_t)(ks * 32) + lchunk;  // byte offset into 64B row

            uint32_t ahi[2][4], w0[4][4];
            #pragma unroll
            for (int am = 0; am < 2; ++am)
                ldsm4(ahi[am], sAhi + (uint32_t)(wm + am * 16 + lrow) * TPITCH + kb);
            #pragma unroll
            for (int bn = 0; bn < 4; ++bn)
                ldsm4(w0[bn], sWhi + (uint32_t)(wn + bn * 16 + lrow) * TPITCH + kb);

            // pass 1: Ahi * Whi
            #pragma unroll
            for (int am = 0; am < 2; ++am)
                #pragma unroll
                for (int bn = 0; bn < 4; ++bn) {
                    mma16816(acc[am][2 * bn],     ahi[am], w0[bn][0], w0[bn][2]);
                    mma16816(acc[am][2 * bn + 1], ahi[am], w0[bn][1], w0[bn][3]);
                }

            // pass 2: Ahi * Wlo
            uint32_t w1[4][4];
            #pragma unroll
            for (int bn = 0; bn < 4; ++bn)
                ldsm4(w1[bn], sWlo + (uint32_t)(wn + bn * 16 + lrow) * TPITCH + kb);
            #pragma unroll
            for (int am = 0; am < 2; ++am)
                #pragma unroll
                for (int bn = 0; bn < 4; ++bn) {
                    mma16816(acc[am][2 * bn],     ahi[am], w1[bn][0], w1[bn][2]);
                    mma16816(acc[am][2 * bn + 1], ahi[am], w1[bn][1], w1[bn][3]);
                }

            // pass 3: Alo * Whi
            uint32_t alo[2][4];
            #pragma unroll
            for (int am = 0; am < 2; ++am)
                ldsm4(alo[am], sAlo + (uint32_t)(wm + am * 16 + lrow) * TPITCH + kb);
            #pragma unroll
            for (int am = 0; am < 2; ++am)
                #pragma unroll
                for (int bn = 0; bn < 4; ++bn) {
                    mma16816(acc[am][2 * bn],     alo[am], w0[bn][0], w0[bn][2]);
                    mma16816(acc[am][2 * bn + 1], alo[am], w0[bn][1], w0[bn][3]);
                }
        }
        __syncthreads();
    }

    // ---- epilogue: accum -> g_gates ----
    int gid = lid >> 2, tig = lid & 3;
    #pragma unroll
    for (int am = 0; am < 2; ++am) {
        #pragma unroll
        for (int bn = 0; bn < 8; ++bn) {
            const float* c = acc[am][bn];
            int row = m0 + wm + am * 16 + gid;
            int col = n0 + wn + bn * 8 + tig * 2;
            float2 v0 = make_float2(c[0], c[1]);
            float2 v1 = make_float2(c[2], c[3]);
            *reinterpret_cast<float2*>(&g_gates[(size_t)row * NDIM + col]) = v0;
            *reinterpret_cast<float2*>(&g_gates[(size_t)(row + 8) * NDIM + col]) = v1;
        }
    }
}

// ===================== kernel 5: activations =====================
__global__ void epilogue_kernel(const float* __restrict__ c_prev, float* __restrict__ out,
                                int n_out) {
    int idx = blockIdx.x * blockDim.x + threadIdx.x;
    int m = idx >> 10, j = idx & 1023;
    const float* gr = g_gates + (size_t)m * NDIM;
    float fp = gr[j]            + g_bias[j];
    float ip = gr[HDIM + j]     + g_bias[HDIM + j];
    float op = gr[2 * HDIM + j] + g_bias[2 * HDIM + j];
    float cp = gr[3 * HDIM + j] + g_bias[3 * HDIM + j];
    float ft = 1.0f / (1.0f + expf(-fp));
    float it = 1.0f / (1.0f + expf(-ip));
    float ot = 1.0f / (1.0f + expf(-op));
    float ct = tanhf(cp);
    float cpv = c_prev[idx];
    float cn = ft * cpv + it * cpv + g_mask[m] * (it * ct);
    float hn = ot * tanhf(cn);
    const int BH = BDIM * HDIM;
    out[idx] = hn;
    if (BH + idx < n_out)     out[BH + idx] = cn;
    if (2 * BH + idx < n_out) out[2 * BH + idx] = ct;
}

// ===================== launcher =====================
extern "C" void kernel_launch(void* const* d_in, const int* in_sizes, int n_in,
                              void* d_out, int out_size) {
    (void)n_in;
    const float* x      = (const float*)d_in[0];
    const float* h_prev = (const float*)d_in[1];
    const float* c_prev = (const float*)d_in[2];
    // d_in[3] = c_prev_tilde_dummy (unused)

    // Input order detection.
    // Dict order (setup_inputs insertion order):
    //   4..19: per gate g in {f,i,o,c}: W_g, bW_g, V_g, bV_g
    //   20..23: bf, bi, bo, bc
    // Signature order (reference() arg order):
    //   per gate: W_g, bW_g, V_g, bV_g, b_g  (4..23 interleaved)
    // Distinguish: in dict order, in_sizes[8] = Wi = 1M; in signature order,
    // in_sizes[8] = bf = 1024.
    const float *W[4], *V[4], *bW[4], *bV[4], *bx[4];
    if (in_sizes[8] > 100000) {
        // dict order
        for (int g = 0; g < 4; ++g) {
            W[g]  = (const float*)d_in[4 + 4 * g];
            bW[g] = (const float*)d_in[5 + 4 * g];
            V[g]  = (const float*)d_in[6 + 4 * g];
            bV[g] = (const float*)d_in[7 + 4 * g];
            bx[g] = (const float*)d_in[20 + g];
        }
    } else {
        // signature order
        for (int g = 0; g < 4; ++g) {
            W[g]  = (const float*)d_in[4 + 5 * g];
            bW[g] = (const float*)d_in[5 + 5 * g];
            V[g]  = (const float*)d_in[6 + 5 * g];
            bV[g] = (const float*)d_in[7 + 5 * g];
            bx[g] = (const float*)d_in[8 + 5 * g];
        }
    }

    convert_A_kernel<<<BDIM, 256>>>(x, h_prev);
    convert_W_kernel<<<NDIM, 256>>>(W[0], W[1], W[2], W[3], V[0], V[1], V[2], V[3]);
    bias_kernel<<<NDIM / 256, 256>>>(bW[0], bV[0], bx[0], bW[1], bV[1], bx[1],
                                     bW[2], bV[2], bx[2], bW[3], bV[3], bx[3]);

    static bool attr_set = false;
    if (!attr_set) {
        cudaFuncSetAttribute(gemm_kernel, cudaFuncAttributeMaxDynamicSharedMemorySize,
                             (int)GEMM_SMEM);
        attr_set = true;
    }
    gemm_kernel<<<dim3(NDIM / BN, BDIM / BM), 256, GEMM_SMEM>>>();

    epilogue_kernel<<<(BDIM * HDIM) / 256, 256>>>(c_prev, (float*)d_out, out_size);
}